// round 2
// baseline (speedup 1.0000x reference)
#include <cuda_runtime.h>
#include <math.h>

#define WMASK 0xffffffffu

// ---------------- Tsit5 tableau (fp32) ----------------
__device__ __forceinline__ float softplus_f(float x) {
    // jax.nn.softplus = logaddexp(x, 0) = max(x,0) + log1p(exp(-|x|))
    return fmaxf(x, 0.0f) + log1pf(expf(-fabsf(x)));
}

__device__ int g_nsum;

__device__ __forceinline__ void mlp_eval(
    const float (&w1)[64], const float (&w2)[32],
    const float (&w3a)[32], const float (&w3b)[32],
    float b1l, float b2l, float b3a, float b3b,
    float a0, float a1, float& o0, float& o1)
{
    // ---- layer 1: h1[lane] = softplus(sum_d W1[lane,d]*arg[d] + b1[lane]) ----
    float acc0 = 0.f, acc1 = 0.f, acc2 = 0.f, acc3 = 0.f;
    #pragma unroll
    for (int d = 0; d < 32; d += 4) {
        float v0 = __shfl_sync(WMASK, a0, d + 0);
        float v1 = __shfl_sync(WMASK, a0, d + 1);
        float v2 = __shfl_sync(WMASK, a0, d + 2);
        float v3 = __shfl_sync(WMASK, a0, d + 3);
        acc0 = fmaf(w1[d + 0], v0, acc0);
        acc1 = fmaf(w1[d + 1], v1, acc1);
        acc2 = fmaf(w1[d + 2], v2, acc2);
        acc3 = fmaf(w1[d + 3], v3, acc3);
    }
    #pragma unroll
    for (int d = 0; d < 32; d += 4) {
        float v0 = __shfl_sync(WMASK, a1, d + 0);
        float v1 = __shfl_sync(WMASK, a1, d + 1);
        float v2 = __shfl_sync(WMASK, a1, d + 2);
        float v3 = __shfl_sync(WMASK, a1, d + 3);
        acc0 = fmaf(w1[32 + d + 0], v0, acc0);
        acc1 = fmaf(w1[32 + d + 1], v1, acc1);
        acc2 = fmaf(w1[32 + d + 2], v2, acc2);
        acc3 = fmaf(w1[32 + d + 3], v3, acc3);
    }
    float h1 = softplus_f((acc0 + acc1) + (acc2 + acc3) + b1l);

    // ---- layer 2: h2[lane] = softplus(sum_j W2[lane,j]*h1[j] + b2[lane]) ----
    float s0 = 0.f, s1 = 0.f, s2 = 0.f, s3 = 0.f;
    #pragma unroll
    for (int j = 0; j < 32; j += 4) {
        float v0 = __shfl_sync(WMASK, h1, j + 0);
        float v1 = __shfl_sync(WMASK, h1, j + 1);
        float v2 = __shfl_sync(WMASK, h1, j + 2);
        float v3 = __shfl_sync(WMASK, h1, j + 3);
        s0 = fmaf(w2[j + 0], v0, s0);
        s1 = fmaf(w2[j + 1], v1, s1);
        s2 = fmaf(w2[j + 2], v2, s2);
        s3 = fmaf(w2[j + 3], v3, s3);
    }
    float h2 = softplus_f((s0 + s1) + (s2 + s3) + b2l);

    // ---- layer 3: out[lane], out[lane+32] ----
    float p0 = 0.f, p1 = 0.f, p2 = 0.f, p3 = 0.f;
    float q0 = 0.f, q1 = 0.f, q2 = 0.f, q3 = 0.f;
    #pragma unroll
    for (int j = 0; j < 32; j += 4) {
        float v0 = __shfl_sync(WMASK, h2, j + 0);
        float v1 = __shfl_sync(WMASK, h2, j + 1);
        float v2 = __shfl_sync(WMASK, h2, j + 2);
        float v3 = __shfl_sync(WMASK, h2, j + 3);
        p0 = fmaf(w3a[j + 0], v0, p0);
        p1 = fmaf(w3a[j + 1], v1, p1);
        p2 = fmaf(w3a[j + 2], v2, p2);
        p3 = fmaf(w3a[j + 3], v3, p3);
        q0 = fmaf(w3b[j + 0], v0, q0);
        q1 = fmaf(w3b[j + 1], v1, q1);
        q2 = fmaf(w3b[j + 2], v2, q2);
        q3 = fmaf(w3b[j + 3], v3, q3);
    }
    o0 = (p0 + p1) + (p2 + p3) + b3a;
    o1 = (q0 + q1) + (q2 + q3) + b3b;
}

__global__ void __launch_bounds__(128)
ode_kernel(const float* __restrict__ x0s,
           const float* __restrict__ W1, const float* __restrict__ b1,
           const float* __restrict__ W2, const float* __restrict__ b2,
           const float* __restrict__ W3, const float* __restrict__ b3,
           const int*   __restrict__ Tp,
           float* __restrict__ out, int B)
{
    const int warp = (blockIdx.x * blockDim.x + threadIdx.x) >> 5;
    const int lane = threadIdx.x & 31;
    if (warp >= B) return;

    // T input: int32 scalar (value ~10). Defensive: if it looks like a float bit
    // pattern, reinterpret.
    int   Ti = *Tp;
    float Tf;
    if (Ti > 0 && Ti < 1000000) Tf = (float)Ti;
    else                        Tf = __int_as_float(Ti);
    const float delta = Tf / 10.0f;   // linspace(0, T, 11) step

    // ---------------- load weights into registers ----------------
    float w1[64], w2[32], w3a[32], w3b[32];
    {
        const float4* p = reinterpret_cast<const float4*>(W1 + lane * 64);
        #pragma unroll
        for (int i = 0; i < 16; ++i) {
            float4 v = p[i];
            w1[4*i+0] = v.x; w1[4*i+1] = v.y; w1[4*i+2] = v.z; w1[4*i+3] = v.w;
        }
    }
    {
        const float4* p = reinterpret_cast<const float4*>(W2 + lane * 32);
        #pragma unroll
        for (int i = 0; i < 8; ++i) {
            float4 v = p[i];
            w2[4*i+0] = v.x; w2[4*i+1] = v.y; w2[4*i+2] = v.z; w2[4*i+3] = v.w;
        }
    }
    {
        const float4* pa = reinterpret_cast<const float4*>(W3 + lane * 32);
        const float4* pb = reinterpret_cast<const float4*>(W3 + (lane + 32) * 32);
        #pragma unroll
        for (int i = 0; i < 8; ++i) {
            float4 va = pa[i];
            w3a[4*i+0] = va.x; w3a[4*i+1] = va.y; w3a[4*i+2] = va.z; w3a[4*i+3] = va.w;
            float4 vb = pb[i];
            w3b[4*i+0] = vb.x; w3b[4*i+1] = vb.y; w3b[4*i+2] = vb.z; w3b[4*i+3] = vb.w;
        }
    }
    const float b1l = b1[lane], b2l = b2[lane];
    const float b3a = b3[lane], b3bv = b3[lane + 32];

    // ---------------- state ----------------
    float y0 = x0s[(size_t)warp * 64 + lane];
    float y1 = x0s[(size_t)warp * 64 + 32 + lane];
    float t  = 0.0f;
    float dt = 1e-3f;
    int   n  = 0;

    const size_t obase = (size_t)warp * 11 * 64;
    out[obase + lane]      = y0;
    out[obase + 32 + lane] = y1;

    // Tsit5 coefficients
    const float A21f = 0.161f;
    const float A31f = -0.008480655492356989f, A32f = 0.335480655492357f;
    const float A41f = 2.8971530571054935f, A42f = -6.359448489975075f, A43f = 4.3622954328695815f;
    const float A51f = 5.325864828439257f, A52f = -11.748883564062828f, A53f = 7.4955393428898365f, A54f = -0.09249506636175525f;
    const float A61f = 5.86145544294642f, A62f = -12.92096931784711f, A63f = 8.159367898576159f, A64f = -0.071584973281401f, A65f = -0.028269050394068383f;
    const float B1f = 0.09646076681806523f, B2f = 0.01f, B3f = 0.4798896504144996f,
                B4f = 1.379008574103742f, B5f = -3.290069515436081f, B6f = 2.324710524099774f;
    const float E1f = -0.00178001105222577714f, E2f = -0.0008164344596567469f, E3f = 0.007880878010261995f,
                E4f = -0.1447110071732629f, E5f = 0.5823571654525552f, E6f = -0.45808210592918697f,
                E7f = 0.015151515151515152f;

    for (int iv = 1; iv <= 10; ++iv) {
        const float t_target = (float)iv * delta;
        for (int it = 0; it < 64; ++it) {
            float remaining = t_target - t;
            if (remaining <= 1e-12f) break;       // done => remaining iters are no-ops
            float h = fminf(dt, fmaxf(remaining, 0.0f));

            float k1_0, k1_1, k2_0, k2_1, k3_0, k3_1, k4_0, k4_1;
            float k5_0, k5_1, k6_0, k6_1, k7_0, k7_1;
            float a0, a1, s0, s1;

            mlp_eval(w1, w2, w3a, w3b, b1l, b2l, b3a, b3bv, y0, y1, k1_0, k1_1);

            a0 = fmaf(h, A21f * k1_0, y0);
            a1 = fmaf(h, A21f * k1_1, y1);
            mlp_eval(w1, w2, w3a, w3b, b1l, b2l, b3a, b3bv, a0, a1, k2_0, k2_1);

            s0 = fmaf(A31f, k1_0, A32f * k2_0);
            s1 = fmaf(A31f, k1_1, A32f * k2_1);
            a0 = fmaf(h, s0, y0); a1 = fmaf(h, s1, y1);
            mlp_eval(w1, w2, w3a, w3b, b1l, b2l, b3a, b3bv, a0, a1, k3_0, k3_1);

            s0 = fmaf(A41f, k1_0, fmaf(A42f, k2_0, A43f * k3_0));
            s1 = fmaf(A41f, k1_1, fmaf(A42f, k2_1, A43f * k3_1));
            a0 = fmaf(h, s0, y0); a1 = fmaf(h, s1, y1);
            mlp_eval(w1, w2, w3a, w3b, b1l, b2l, b3a, b3bv, a0, a1, k4_0, k4_1);

            s0 = fmaf(A51f, k1_0, fmaf(A52f, k2_0, fmaf(A53f, k3_0, A54f * k4_0)));
            s1 = fmaf(A51f, k1_1, fmaf(A52f, k2_1, fmaf(A53f, k3_1, A54f * k4_1)));
            a0 = fmaf(h, s0, y0); a1 = fmaf(h, s1, y1);
            mlp_eval(w1, w2, w3a, w3b, b1l, b2l, b3a, b3bv, a0, a1, k5_0, k5_1);

            s0 = fmaf(A61f, k1_0, fmaf(A62f, k2_0, fmaf(A63f, k3_0, fmaf(A64f, k4_0, A65f * k5_0))));
            s1 = fmaf(A61f, k1_1, fmaf(A62f, k2_1, fmaf(A63f, k3_1, fmaf(A64f, k4_1, A65f * k5_1))));
            a0 = fmaf(h, s0, y0); a1 = fmaf(h, s1, y1);
            mlp_eval(w1, w2, w3a, w3b, b1l, b2l, b3a, b3bv, a0, a1, k6_0, k6_1);

            s0 = fmaf(B1f, k1_0, fmaf(B2f, k2_0, fmaf(B3f, k3_0, fmaf(B4f, k4_0, fmaf(B5f, k5_0, B6f * k6_0)))));
            s1 = fmaf(B1f, k1_1, fmaf(B2f, k2_1, fmaf(B3f, k3_1, fmaf(B4f, k4_1, fmaf(B5f, k5_1, B6f * k6_1)))));
            float y5_0 = fmaf(h, s0, y0);
            float y5_1 = fmaf(h, s1, y1);
            mlp_eval(w1, w2, w3a, w3b, b1l, b2l, b3a, b3bv, y5_0, y5_1, k7_0, k7_1);

            float e0 = fmaf(E1f, k1_0, fmaf(E2f, k2_0, fmaf(E3f, k3_0, fmaf(E4f, k4_0,
                       fmaf(E5f, k5_0, fmaf(E6f, k6_0, E7f * k7_0))))));
            float e1 = fmaf(E1f, k1_1, fmaf(E2f, k2_1, fmaf(E3f, k3_1, fmaf(E4f, k4_1,
                       fmaf(E5f, k5_1, fmaf(E6f, k6_1, E7f * k7_1))))));
            float err0 = h * e0, err1 = h * e1;
            float sc0 = fmaf(1e-3f, fmaxf(fabsf(y0), fabsf(y5_0)), 1e-6f);
            float sc1 = fmaf(1e-3f, fmaxf(fabsf(y1), fabsf(y5_1)), 1e-6f);
            float r0 = err0 / sc0, r1 = err1 / sc1;
            float local = fmaf(r0, r0, r1 * r1);
            #pragma unroll
            for (int off = 16; off > 0; off >>= 1)
                local += __shfl_xor_sync(WMASK, local, off);
            float enorm = fmaxf(sqrtf(local * (1.0f / 64.0f)), 1e-10f);

            bool accept = (enorm <= 1.0f);
            float fac = fminf(fmaxf(0.9f * powf(enorm, -0.2f), 0.1f), 5.0f);
            if (accept) { t += h; y0 = y5_0; y1 = y5_1; }
            dt = fmaxf(h * fac, 1e-8f);
            n += 1;
        }
        out[obase + (size_t)iv * 64 + lane]      = y0;
        out[obase + (size_t)iv * 64 + 32 + lane] = y1;
    }

    if (lane == 0) atomicAdd(&g_nsum, n);
}

__global__ void init_kernel() { g_nsum = 0; }

__global__ void finish_kernel(float* out, long long traj_elems, long long out_size) {
    long long i = traj_elems + (long long)blockIdx.x * blockDim.x + threadIdx.x;
    if (i < out_size) out[i] = (float)g_nsum;
}

extern "C" void kernel_launch(void* const* d_in, const int* in_sizes, int n_in,
                              void* d_out, int out_size) {
    const float* x0s = (const float*)d_in[0];
    const float* W1  = (const float*)d_in[1];
    const float* b1  = (const float*)d_in[2];
    const float* W2  = (const float*)d_in[3];
    const float* b2  = (const float*)d_in[4];
    const float* W3  = (const float*)d_in[5];
    const float* b3  = (const float*)d_in[6];
    const int*   Tp  = (const int*)d_in[7];
    float* out = (float*)d_out;

    const int B = in_sizes[0] / 64;
    init_kernel<<<1, 1>>>();
    const int threads = 128;
    const int blocks = (B * 32 + threads - 1) / threads;
    ode_kernel<<<blocks, threads>>>(x0s, W1, b1, W2, b2, W3, b3, Tp, out, B);

    long long traj_elems = (long long)B * 11 * 64;
    if ((long long)out_size > traj_elems) {
        long long tail = (long long)out_size - traj_elems;
        int tb = (int)((tail + 63) / 64);
        finish_kernel<<<tb, 64>>>(out, traj_elems, (long long)out_size);
    }
}

// round 5
// speedup vs baseline: 1.1276x; 1.1276x over previous
#include <cuda_runtime.h>
#include <math.h>

#define WMASK 0xffffffffu

__device__ __forceinline__ float softplus_f(float x) {
    // jax.nn.softplus = logaddexp(x, 0) = max(x,0) + log1p(exp(-|x|))
    return fmaxf(x, 0.0f) + log1pf(expf(-fabsf(x)));
}

__device__ __forceinline__ void mlp_eval(
    const float (&w1)[64], const float (&w2)[32],
    const float (&w3a)[32], const float (&w3b)[32],
    float b1l, float b2l, float b3a, float b3b,
    float a0, float a1, float& o0, float& o1)
{
    // ---- layer 1 ----
    float acc0 = 0.f, acc1 = 0.f, acc2 = 0.f, acc3 = 0.f;
    #pragma unroll
    for (int d = 0; d < 32; d += 4) {
        float v0 = __shfl_sync(WMASK, a0, d + 0);
        float v1 = __shfl_sync(WMASK, a0, d + 1);
        float v2 = __shfl_sync(WMASK, a0, d + 2);
        float v3 = __shfl_sync(WMASK, a0, d + 3);
        acc0 = fmaf(w1[d + 0], v0, acc0);
        acc1 = fmaf(w1[d + 1], v1, acc1);
        acc2 = fmaf(w1[d + 2], v2, acc2);
        acc3 = fmaf(w1[d + 3], v3, acc3);
    }
    #pragma unroll
    for (int d = 0; d < 32; d += 4) {
        float v0 = __shfl_sync(WMASK, a1, d + 0);
        float v1 = __shfl_sync(WMASK, a1, d + 1);
        float v2 = __shfl_sync(WMASK, a1, d + 2);
        float v3 = __shfl_sync(WMASK, a1, d + 3);
        acc0 = fmaf(w1[32 + d + 0], v0, acc0);
        acc1 = fmaf(w1[32 + d + 1], v1, acc1);
        acc2 = fmaf(w1[32 + d + 2], v2, acc2);
        acc3 = fmaf(w1[32 + d + 3], v3, acc3);
    }
    float h1 = softplus_f((acc0 + acc1) + (acc2 + acc3) + b1l);

    // ---- layer 2 ----
    float s0 = 0.f, s1 = 0.f, s2 = 0.f, s3 = 0.f;
    #pragma unroll
    for (int j = 0; j < 32; j += 4) {
        float v0 = __shfl_sync(WMASK, h1, j + 0);
        float v1 = __shfl_sync(WMASK, h1, j + 1);
        float v2 = __shfl_sync(WMASK, h1, j + 2);
        float v3 = __shfl_sync(WMASK, h1, j + 3);
        s0 = fmaf(w2[j + 0], v0, s0);
        s1 = fmaf(w2[j + 1], v1, s1);
        s2 = fmaf(w2[j + 2], v2, s2);
        s3 = fmaf(w2[j + 3], v3, s3);
    }
    float h2 = softplus_f((s0 + s1) + (s2 + s3) + b2l);

    // ---- layer 3 ----
    float p0 = 0.f, p1 = 0.f, p2 = 0.f, p3 = 0.f;
    float q0 = 0.f, q1 = 0.f, q2 = 0.f, q3 = 0.f;
    #pragma unroll
    for (int j = 0; j < 32; j += 4) {
        float v0 = __shfl_sync(WMASK, h2, j + 0);
        float v1 = __shfl_sync(WMASK, h2, j + 1);
        float v2 = __shfl_sync(WMASK, h2, j + 2);
        float v3 = __shfl_sync(WMASK, h2, j + 3);
        p0 = fmaf(w3a[j + 0], v0, p0);
        p1 = fmaf(w3a[j + 1], v1, p1);
        p2 = fmaf(w3a[j + 2], v2, p2);
        p3 = fmaf(w3a[j + 3], v3, p3);
        q0 = fmaf(w3b[j + 0], v0, q0);
        q1 = fmaf(w3b[j + 1], v1, q1);
        q2 = fmaf(w3b[j + 2], v2, q2);
        q3 = fmaf(w3b[j + 3], v3, q3);
    }
    o0 = (p0 + p1) + (p2 + p3) + b3a;
    o1 = (q0 + q1) + (q2 + q3) + b3b;
}

__global__ void __launch_bounds__(64)
ode_kernel(const float* __restrict__ x0s,
           const float* __restrict__ W1, const float* __restrict__ b1,
           const float* __restrict__ W2, const float* __restrict__ b2,
           const float* __restrict__ W3, const float* __restrict__ b3,
           const int*   __restrict__ Tp,
           float* __restrict__ out, float* __restrict__ nsum_out, int B)
{
    const int warp = (blockIdx.x * blockDim.x + threadIdx.x) >> 5;
    const int lane = threadIdx.x & 31;
    if (warp >= B) return;

    int   Ti = *Tp;
    float Tf;
    if (Ti > 0 && Ti < 1000000) Tf = (float)Ti;
    else                        Tf = __int_as_float(Ti);
    const float delta = Tf / 10.0f;

    // ---------------- weights to registers ----------------
    float w1[64], w2[32], w3a[32], w3b[32];
    {
        const float4* p = reinterpret_cast<const float4*>(W1 + lane * 64);
        #pragma unroll
        for (int i = 0; i < 16; ++i) {
            float4 v = p[i];
            w1[4*i+0] = v.x; w1[4*i+1] = v.y; w1[4*i+2] = v.z; w1[4*i+3] = v.w;
        }
    }
    {
        const float4* p = reinterpret_cast<const float4*>(W2 + lane * 32);
        #pragma unroll
        for (int i = 0; i < 8; ++i) {
            float4 v = p[i];
            w2[4*i+0] = v.x; w2[4*i+1] = v.y; w2[4*i+2] = v.z; w2[4*i+3] = v.w;
        }
    }
    {
        const float4* pa = reinterpret_cast<const float4*>(W3 + lane * 32);
        const float4* pb = reinterpret_cast<const float4*>(W3 + (lane + 32) * 32);
        #pragma unroll
        for (int i = 0; i < 8; ++i) {
            float4 va = pa[i];
            w3a[4*i+0] = va.x; w3a[4*i+1] = va.y; w3a[4*i+2] = va.z; w3a[4*i+3] = va.w;
            float4 vb = pb[i];
            w3b[4*i+0] = vb.x; w3b[4*i+1] = vb.y; w3b[4*i+2] = vb.z; w3b[4*i+3] = vb.w;
        }
    }
    const float b1l = b1[lane], b2l = b2[lane];
    const float b3a = b3[lane], b3bv = b3[lane + 32];

    // ---------------- state ----------------
    float y0 = x0s[(size_t)warp * 64 + lane];
    float y1 = x0s[(size_t)warp * 64 + 32 + lane];
    float t  = 0.0f;
    float dt = 1e-3f;
    int   n  = 0;

    const size_t obase = (size_t)warp * 11 * 64;
    out[obase + lane]      = y0;
    out[obase + 32 + lane] = y1;

    const float A21f = 0.161f;
    const float A31f = -0.008480655492356989f, A32f = 0.335480655492357f;
    const float A41f = 2.8971530571054935f, A42f = -6.359448489975075f, A43f = 4.3622954328695815f;
    const float A51f = 5.325864828439257f, A52f = -11.748883564062828f, A53f = 7.4955393428898365f, A54f = -0.09249506636175525f;
    const float A61f = 5.86145544294642f, A62f = -12.92096931784711f, A63f = 8.159367898576159f, A64f = -0.071584973281401f, A65f = -0.028269050394068383f;
    const float B1f = 0.09646076681806523f, B2f = 0.01f, B3f = 0.4798896504144996f,
                B4f = 1.379008574103742f, B5f = -3.290069515436081f, B6f = 2.324710524099774f;
    const float E1f = -0.00178001105222577714f, E2f = -0.0008164344596567469f, E3f = 0.007880878010261995f,
                E4f = -0.1447110071732629f, E5f = 0.5823571654525552f, E6f = -0.45808210592918697f,
                E7f = 0.015151515151515152f;

    // FSAL: maintain invariant k1 == f(y). Computed once here; afterwards,
    // accept => y := y5 and k1 := k7 (bit-identical to recomputing f(y5));
    // reject => y unchanged, k1 unchanged. Matches reference numerics exactly.
    float k1_0, k1_1;
    mlp_eval(w1, w2, w3a, w3b, b1l, b2l, b3a, b3bv, y0, y1, k1_0, k1_1);

    for (int iv = 1; iv <= 10; ++iv) {
        const float t_target = (float)iv * delta;
        for (int it = 0; it < 64; ++it) {
            float remaining = t_target - t;
            if (remaining <= 1e-12f) break;
            float h = fminf(dt, fmaxf(remaining, 0.0f));

            float k2_0, k2_1, k3_0, k3_1, k4_0, k4_1;
            float k5_0, k5_1, k6_0, k6_1, k7_0, k7_1;
            float a0, a1, s0, s1;

            a0 = fmaf(h, A21f * k1_0, y0);
            a1 = fmaf(h, A21f * k1_1, y1);
            mlp_eval(w1, w2, w3a, w3b, b1l, b2l, b3a, b3bv, a0, a1, k2_0, k2_1);

            s0 = fmaf(A31f, k1_0, A32f * k2_0);
            s1 = fmaf(A31f, k1_1, A32f * k2_1);
            a0 = fmaf(h, s0, y0); a1 = fmaf(h, s1, y1);
            mlp_eval(w1, w2, w3a, w3b, b1l, b2l, b3a, b3bv, a0, a1, k3_0, k3_1);

            s0 = fmaf(A41f, k1_0, fmaf(A42f, k2_0, A43f * k3_0));
            s1 = fmaf(A41f, k1_1, fmaf(A42f, k2_1, A43f * k3_1));
            a0 = fmaf(h, s0, y0); a1 = fmaf(h, s1, y1);
            mlp_eval(w1, w2, w3a, w3b, b1l, b2l, b3a, b3bv, a0, a1, k4_0, k4_1);

            s0 = fmaf(A51f, k1_0, fmaf(A52f, k2_0, fmaf(A53f, k3_0, A54f * k4_0)));
            s1 = fmaf(A51f, k1_1, fmaf(A52f, k2_1, fmaf(A53f, k3_1, A54f * k4_1)));
            a0 = fmaf(h, s0, y0); a1 = fmaf(h, s1, y1);
            mlp_eval(w1, w2, w3a, w3b, b1l, b2l, b3a, b3bv, a0, a1, k5_0, k5_1);

            s0 = fmaf(A61f, k1_0, fmaf(A62f, k2_0, fmaf(A63f, k3_0, fmaf(A64f, k4_0, A65f * k5_0))));
            s1 = fmaf(A61f, k1_1, fmaf(A62f, k2_1, fmaf(A63f, k3_1, fmaf(A64f, k4_1, A65f * k5_1))));
            a0 = fmaf(h, s0, y0); a1 = fmaf(h, s1, y1);
            mlp_eval(w1, w2, w3a, w3b, b1l, b2l, b3a, b3bv, a0, a1, k6_0, k6_1);

            s0 = fmaf(B1f, k1_0, fmaf(B2f, k2_0, fmaf(B3f, k3_0, fmaf(B4f, k4_0, fmaf(B5f, k5_0, B6f * k6_0)))));
            s1 = fmaf(B1f, k1_1, fmaf(B2f, k2_1, fmaf(B3f, k3_1, fmaf(B4f, k4_1, fmaf(B5f, k5_1, B6f * k6_1)))));
            float y5_0 = fmaf(h, s0, y0);
            float y5_1 = fmaf(h, s1, y1);
            mlp_eval(w1, w2, w3a, w3b, b1l, b2l, b3a, b3bv, y5_0, y5_1, k7_0, k7_1);

            float e0 = fmaf(E1f, k1_0, fmaf(E2f, k2_0, fmaf(E3f, k3_0, fmaf(E4f, k4_0,
                       fmaf(E5f, k5_0, fmaf(E6f, k6_0, E7f * k7_0))))));
            float e1 = fmaf(E1f, k1_1, fmaf(E2f, k2_1, fmaf(E3f, k3_1, fmaf(E4f, k4_1,
                       fmaf(E5f, k5_1, fmaf(E6f, k6_1, E7f * k7_1))))));
            float err0 = h * e0, err1 = h * e1;
            float sc0 = fmaf(1e-3f, fmaxf(fabsf(y0), fabsf(y5_0)), 1e-6f);
            float sc1 = fmaf(1e-3f, fmaxf(fabsf(y1), fabsf(y5_1)), 1e-6f);
            float r0 = err0 / sc0, r1 = err1 / sc1;
            float local = fmaf(r0, r0, r1 * r1);
            #pragma unroll
            for (int off = 16; off > 0; off >>= 1)
                local += __shfl_xor_sync(WMASK, local, off);
            float enorm = fmaxf(sqrtf(local * (1.0f / 64.0f)), 1e-10f);

            bool accept = (enorm <= 1.0f);
            float fac = fminf(fmaxf(0.9f * powf(enorm, -0.2f), 0.1f), 5.0f);
            if (accept) {
                t += h; y0 = y5_0; y1 = y5_1;
                k1_0 = k7_0; k1_1 = k7_1;   // FSAL: f(y_new) == k7
            }
            dt = fmaxf(h * fac, 1e-8f);
            n += 1;
        }
        out[obase + (size_t)iv * 64 + lane]      = y0;
        out[obase + (size_t)iv * 64 + 32 + lane] = y1;
    }

    if (lane == 0) atomicAdd(nsum_out, (float)n);
}

// Only used if the output tail has more than one element (expected: exactly 1).
__global__ void replicate_tail_kernel(float* tail, long long tail_elems) {
    long long i = (long long)blockIdx.x * blockDim.x + threadIdx.x;
    if (i > 0 && i < tail_elems) tail[i] = tail[0];
}

extern "C" void kernel_launch(void* const* d_in, const int* in_sizes, int n_in,
                              void* d_out, int out_size) {
    const float* x0s = (const float*)d_in[0];
    const float* W1  = (const float*)d_in[1];
    const float* b1  = (const float*)d_in[2];
    const float* W2  = (const float*)d_in[3];
    const float* b2  = (const float*)d_in[4];
    const float* W3  = (const float*)d_in[5];
    const float* b3  = (const float*)d_in[6];
    const int*   Tp  = (const int*)d_in[7];
    float* out = (float*)d_out;

    const int B = in_sizes[0] / 64;
    const long long traj_elems = (long long)B * 11 * 64;
    const long long tail = (long long)out_size - traj_elems;

    // Zero the step-count accumulator (memset node — not a kernel launch, so
    // ncu's launch-indexed capture lands on ode_kernel).
    if (tail > 0)
        cudaMemsetAsync(out + traj_elems, 0, (size_t)tail * sizeof(float), 0);

    const int threads = 64;                 // 2 warps/block for fine-grained balancing
    const int blocks = (B * 32 + threads - 1) / threads;
    ode_kernel<<<blocks, threads>>>(x0s, W1, b1, W2, b2, W3, b3, Tp,
                                    out, out + traj_elems, B);

    if (tail > 1) {
        int tb = (int)((tail + 63) / 64);
        replicate_tail_kernel<<<tb, 64>>>(out + traj_elems, tail);
    }
}

// round 7
// speedup vs baseline: 1.3882x; 1.2311x over previous
#include <cuda_runtime.h>
#include <math.h>

#define WMASK 0xffffffffu

__device__ __forceinline__ float softplus_f(float x) {
    // jax.nn.softplus = logaddexp(x, 0) = max(x,0) + log1p(exp(-|x|))
    return fmaxf(x, 0.0f) + log1pf(expf(-fabsf(x)));
}

// Warp-uniform broadcast matvec via shared memory.
// sbuf: 64-float staging (argument vector), sh1/sh2: 32-float hidden staging.
// All LDS reads are same-address across the warp => conflict-free broadcast.
// Accumulation order matches the original SHFL version bit-for-bit:
// acc_k sums dims d ≡ k (mod 4) in increasing d.
__device__ __forceinline__ void mlp_eval(
    const float (&w1)[64], const float (&w2)[32],
    const float (&w3a)[32], const float (&w3b)[32],
    float b1l, float b2l, float b3a, float b3b,
    float* __restrict__ sbuf, float* __restrict__ sh1, float* __restrict__ sh2,
    int lane,
    float a0, float a1, float& o0, float& o1)
{
    // ---- stage argument into smem (lane owns dims lane, lane+32) ----
    sbuf[lane]      = a0;
    sbuf[lane + 32] = a1;
    __syncwarp();

    // ---- layer 1 ----
    float acc0 = 0.f, acc1 = 0.f, acc2 = 0.f, acc3 = 0.f;
    const float4* v64 = reinterpret_cast<const float4*>(sbuf);
    #pragma unroll
    for (int i = 0; i < 16; ++i) {
        float4 v = v64[i];
        acc0 = fmaf(w1[4*i + 0], v.x, acc0);
        acc1 = fmaf(w1[4*i + 1], v.y, acc1);
        acc2 = fmaf(w1[4*i + 2], v.z, acc2);
        acc3 = fmaf(w1[4*i + 3], v.w, acc3);
    }
    float h1 = softplus_f((acc0 + acc1) + (acc2 + acc3) + b1l);

    // ---- layer 2 ----
    sh1[lane] = h1;
    __syncwarp();
    float s0 = 0.f, s1 = 0.f, s2 = 0.f, s3 = 0.f;
    const float4* v32 = reinterpret_cast<const float4*>(sh1);
    #pragma unroll
    for (int i = 0; i < 8; ++i) {
        float4 v = v32[i];
        s0 = fmaf(w2[4*i + 0], v.x, s0);
        s1 = fmaf(w2[4*i + 1], v.y, s1);
        s2 = fmaf(w2[4*i + 2], v.z, s2);
        s3 = fmaf(w2[4*i + 3], v.w, s3);
    }
    float h2 = softplus_f((s0 + s1) + (s2 + s3) + b2l);

    // ---- layer 3 ----
    sh2[lane] = h2;
    __syncwarp();
    float p0 = 0.f, p1 = 0.f, p2 = 0.f, p3 = 0.f;
    float q0 = 0.f, q1 = 0.f, q2 = 0.f, q3 = 0.f;
    const float4* h24 = reinterpret_cast<const float4*>(sh2);
    #pragma unroll
    for (int i = 0; i < 8; ++i) {
        float4 v = h24[i];
        p0 = fmaf(w3a[4*i + 0], v.x, p0);
        p1 = fmaf(w3a[4*i + 1], v.y, p1);
        p2 = fmaf(w3a[4*i + 2], v.z, p2);
        p3 = fmaf(w3a[4*i + 3], v.w, p3);
        q0 = fmaf(w3b[4*i + 0], v.x, q0);
        q1 = fmaf(w3b[4*i + 1], v.y, q1);
        q2 = fmaf(w3b[4*i + 2], v.z, q2);
        q3 = fmaf(w3b[4*i + 3], v.w, q3);
    }
    o0 = (p0 + p1) + (p2 + p3) + b3a;
    o1 = (q0 + q1) + (q2 + q3) + b3b;
}

__global__ void __launch_bounds__(64)
ode_kernel(const float* __restrict__ x0s,
           const float* __restrict__ W1, const float* __restrict__ b1,
           const float* __restrict__ W2, const float* __restrict__ b2,
           const float* __restrict__ W3, const float* __restrict__ b3,
           const int*   __restrict__ Tp,
           float* __restrict__ out, float* __restrict__ nsum_out, int B)
{
    __shared__ __align__(16) float s_arg[2][64];
    __shared__ __align__(16) float s_h1[2][32];
    __shared__ __align__(16) float s_h2[2][32];

    const int warp  = (blockIdx.x * blockDim.x + threadIdx.x) >> 5;
    const int wloc  = (threadIdx.x >> 5) & 1;
    const int lane  = threadIdx.x & 31;
    if (warp >= B) return;

    float* sbuf = s_arg[wloc];
    float* sh1  = s_h1[wloc];
    float* sh2  = s_h2[wloc];

    int   Ti = *Tp;
    float Tf;
    if (Ti > 0 && Ti < 1000000) Tf = (float)Ti;
    else                        Tf = __int_as_float(Ti);
    const float delta = Tf / 10.0f;

    // ---------------- weights to registers ----------------
    float w1[64], w2[32], w3a[32], w3b[32];
    {
        const float4* p = reinterpret_cast<const float4*>(W1 + lane * 64);
        #pragma unroll
        for (int i = 0; i < 16; ++i) {
            float4 v = p[i];
            w1[4*i+0] = v.x; w1[4*i+1] = v.y; w1[4*i+2] = v.z; w1[4*i+3] = v.w;
        }
    }
    {
        const float4* p = reinterpret_cast<const float4*>(W2 + lane * 32);
        #pragma unroll
        for (int i = 0; i < 8; ++i) {
            float4 v = p[i];
            w2[4*i+0] = v.x; w2[4*i+1] = v.y; w2[4*i+2] = v.z; w2[4*i+3] = v.w;
        }
    }
    {
        const float4* pa = reinterpret_cast<const float4*>(W3 + lane * 32);
        const float4* pb = reinterpret_cast<const float4*>(W3 + (lane + 32) * 32);
        #pragma unroll
        for (int i = 0; i < 8; ++i) {
            float4 va = pa[i];
            w3a[4*i+0] = va.x; w3a[4*i+1] = va.y; w3a[4*i+2] = va.z; w3a[4*i+3] = va.w;
            float4 vb = pb[i];
            w3b[4*i+0] = vb.x; w3b[4*i+1] = vb.y; w3b[4*i+2] = vb.z; w3b[4*i+3] = vb.w;
        }
    }
    const float b1l = b1[lane], b2l = b2[lane];
    const float b3a = b3[lane], b3bv = b3[lane + 32];

    // ---------------- state ----------------
    float y0 = x0s[(size_t)warp * 64 + lane];
    float y1 = x0s[(size_t)warp * 64 + 32 + lane];
    float t  = 0.0f;
    float dt = 1e-3f;
    int   n  = 0;

    const size_t obase = (size_t)warp * 11 * 64;
    out[obase + lane]      = y0;
    out[obase + 32 + lane] = y1;

    const float A21f = 0.161f;
    const float A31f = -0.008480655492356989f, A32f = 0.335480655492357f;
    const float A41f = 2.8971530571054935f, A42f = -6.359448489975075f, A43f = 4.3622954328695815f;
    const float A51f = 5.325864828439257f, A52f = -11.748883564062828f, A53f = 7.4955393428898365f, A54f = -0.09249506636175525f;
    const float A61f = 5.86145544294642f, A62f = -12.92096931784711f, A63f = 8.159367898576159f, A64f = -0.071584973281401f, A65f = -0.028269050394068383f;
    const float B1f = 0.09646076681806523f, B2f = 0.01f, B3f = 0.4798896504144996f,
                B4f = 1.379008574103742f, B5f = -3.290069515436081f, B6f = 2.324710524099774f;
    const float E1f = -0.00178001105222577714f, E2f = -0.0008164344596567469f, E3f = 0.007880878010261995f,
                E4f = -0.1447110071732629f, E5f = 0.5823571654525552f, E6f = -0.45808210592918697f,
                E7f = 0.015151515151515152f;

    // FSAL invariant: k1 == f(y) at loop top. accept => k1 := k7 (bit-identical
    // to recomputing f(y5)); reject => unchanged. Matches reference numerics.
    float k1_0, k1_1;
    mlp_eval(w1, w2, w3a, w3b, b1l, b2l, b3a, b3bv, sbuf, sh1, sh2, lane,
             y0, y1, k1_0, k1_1);

    for (int iv = 1; iv <= 10; ++iv) {
        const float t_target = (float)iv * delta;
        for (int it = 0; it < 64; ++it) {
            float remaining = t_target - t;
            if (remaining <= 1e-12f) break;
            float h = fminf(dt, fmaxf(remaining, 0.0f));

            float k2_0, k2_1, k3_0, k3_1, k4_0, k4_1;
            float k5_0, k5_1, k6_0, k6_1, k7_0, k7_1;
            float a0, a1, s0, s1;

            a0 = fmaf(h, A21f * k1_0, y0);
            a1 = fmaf(h, A21f * k1_1, y1);
            mlp_eval(w1, w2, w3a, w3b, b1l, b2l, b3a, b3bv, sbuf, sh1, sh2, lane,
                     a0, a1, k2_0, k2_1);

            s0 = fmaf(A31f, k1_0, A32f * k2_0);
            s1 = fmaf(A31f, k1_1, A32f * k2_1);
            a0 = fmaf(h, s0, y0); a1 = fmaf(h, s1, y1);
            mlp_eval(w1, w2, w3a, w3b, b1l, b2l, b3a, b3bv, sbuf, sh1, sh2, lane,
                     a0, a1, k3_0, k3_1);

            s0 = fmaf(A41f, k1_0, fmaf(A42f, k2_0, A43f * k3_0));
            s1 = fmaf(A41f, k1_1, fmaf(A42f, k2_1, A43f * k3_1));
            a0 = fmaf(h, s0, y0); a1 = fmaf(h, s1, y1);
            mlp_eval(w1, w2, w3a, w3b, b1l, b2l, b3a, b3bv, sbuf, sh1, sh2, lane,
                     a0, a1, k4_0, k4_1);

            s0 = fmaf(A51f, k1_0, fmaf(A52f, k2_0, fmaf(A53f, k3_0, A54f * k4_0)));
            s1 = fmaf(A51f, k1_1, fmaf(A52f, k2_1, fmaf(A53f, k3_1, A54f * k4_1)));
            a0 = fmaf(h, s0, y0); a1 = fmaf(h, s1, y1);
            mlp_eval(w1, w2, w3a, w3b, b1l, b2l, b3a, b3bv, sbuf, sh1, sh2, lane,
                     a0, a1, k5_0, k5_1);

            s0 = fmaf(A61f, k1_0, fmaf(A62f, k2_0, fmaf(A63f, k3_0, fmaf(A64f, k4_0, A65f * k5_0))));
            s1 = fmaf(A61f, k1_1, fmaf(A62f, k2_1, fmaf(A63f, k3_1, fmaf(A64f, k4_1, A65f * k5_1))));
            a0 = fmaf(h, s0, y0); a1 = fmaf(h, s1, y1);
            mlp_eval(w1, w2, w3a, w3b, b1l, b2l, b3a, b3bv, sbuf, sh1, sh2, lane,
                     a0, a1, k6_0, k6_1);

            s0 = fmaf(B1f, k1_0, fmaf(B2f, k2_0, fmaf(B3f, k3_0, fmaf(B4f, k4_0, fmaf(B5f, k5_0, B6f * k6_0)))));
            s1 = fmaf(B1f, k1_1, fmaf(B2f, k2_1, fmaf(B3f, k3_1, fmaf(B4f, k4_1, fmaf(B5f, k5_1, B6f * k6_1)))));
            float y5_0 = fmaf(h, s0, y0);
            float y5_1 = fmaf(h, s1, y1);
            mlp_eval(w1, w2, w3a, w3b, b1l, b2l, b3a, b3bv, sbuf, sh1, sh2, lane,
                     y5_0, y5_1, k7_0, k7_1);

            float e0 = fmaf(E1f, k1_0, fmaf(E2f, k2_0, fmaf(E3f, k3_0, fmaf(E4f, k4_0,
                       fmaf(E5f, k5_0, fmaf(E6f, k6_0, E7f * k7_0))))));
            float e1 = fmaf(E1f, k1_1, fmaf(E2f, k2_1, fmaf(E3f, k3_1, fmaf(E4f, k4_1,
                       fmaf(E5f, k5_1, fmaf(E6f, k6_1, E7f * k7_1))))));
            float err0 = h * e0, err1 = h * e1;
            float sc0 = fmaf(1e-3f, fmaxf(fabsf(y0), fabsf(y5_0)), 1e-6f);
            float sc1 = fmaf(1e-3f, fmaxf(fabsf(y1), fabsf(y5_1)), 1e-6f);
            float r0 = err0 / sc0, r1 = err1 / sc1;
            float local = fmaf(r0, r0, r1 * r1);
            #pragma unroll
            for (int off = 16; off > 0; off >>= 1)
                local += __shfl_xor_sync(WMASK, local, off);
            float enorm = fmaxf(sqrtf(local * (1.0f / 64.0f)), 1e-10f);

            bool accept = (enorm <= 1.0f);
            float fac = fminf(fmaxf(0.9f * powf(enorm, -0.2f), 0.1f), 5.0f);
            if (accept) {
                t += h; y0 = y5_0; y1 = y5_1;
                k1_0 = k7_0; k1_1 = k7_1;   // FSAL
            }
            dt = fmaxf(h * fac, 1e-8f);
            n += 1;
        }
        out[obase + (size_t)iv * 64 + lane]      = y0;
        out[obase + (size_t)iv * 64 + 32 + lane] = y1;
    }

    if (lane == 0) atomicAdd(nsum_out, (float)n);
}

// Only used if the output tail has more than one element (expected: exactly 1).
__global__ void replicate_tail_kernel(float* tail, long long tail_elems) {
    long long i = (long long)blockIdx.x * blockDim.x + threadIdx.x;
    if (i > 0 && i < tail_elems) tail[i] = tail[0];
}

extern "C" void kernel_launch(void* const* d_in, const int* in_sizes, int n_in,
                              void* d_out, int out_size) {
    const float* x0s = (const float*)d_in[0];
    const float* W1  = (const float*)d_in[1];
    const float* b1  = (const float*)d_in[2];
    const float* W2  = (const float*)d_in[3];
    const float* b2  = (const float*)d_in[4];
    const float* W3  = (const float*)d_in[5];
    const float* b3  = (const float*)d_in[6];
    const int*   Tp  = (const int*)d_in[7];
    float* out = (float*)d_out;

    const int B = in_sizes[0] / 64;
    const long long traj_elems = (long long)B * 11 * 64;
    const long long tail = (long long)out_size - traj_elems;

    if (tail > 0)
        cudaMemsetAsync(out + traj_elems, 0, (size_t)tail * sizeof(float), 0);

    const int threads = 64;
    const int blocks = (B * 32 + threads - 1) / threads;
    ode_kernel<<<blocks, threads>>>(x0s, W1, b1, W2, b2, W3, b3, Tp,
                                    out, out + traj_elems, B);

    if (tail > 1) {
        int tb = (int)((tail + 63) / 64);
        replicate_tail_kernel<<<tb, 64>>>(out + traj_elems, tail);
    }
}

// round 9
// speedup vs baseline: 1.4468x; 1.0422x over previous
#include <cuda_runtime.h>
#include <math.h>

#define WMASK 0xffffffffu

__device__ __forceinline__ float softplus_f(float x) {
    // jax.nn.softplus = logaddexp(x, 0) = max(x,0) + log1p(exp(-|x|))
    return fmaxf(x, 0.0f) + log1pf(expf(-fabsf(x)));
}

// Packed dual FMA: two independent fp32 RN fmas in one instruction (sm_100+).
__device__ __forceinline__ unsigned long long ffma2(
    unsigned long long a, unsigned long long b, unsigned long long c)
{
    unsigned long long d;
    asm("fma.rn.f32x2 %0, %1, %2, %3;" : "=l"(d) : "l"(a), "l"(b), "l"(c));
    return d;
}

__device__ __forceinline__ float2 unpack2(unsigned long long v) {
    float2 r;
    asm("mov.b64 {%0, %1}, %2;" : "=f"(r.x), "=f"(r.y) : "l"(v));
    return r;
}

// Warp-uniform broadcast matvec via shared memory + packed f32x2 FMAs.
// Weight pairs are contiguous in each row => packed registers load for free.
// Vector pairs come from the (16B-aligned) smem staging buffers reinterpreted
// as ulonglong2 => no packing MOVs. Each f32x2 half is an exact fp32 RN fma,
// and accumulator partitioning matches the scalar version bit-for-bit:
// packed acc01 = (sum of dims ≡0 mod 4, sum of dims ≡1 mod 4), etc.
__device__ __forceinline__ void mlp_eval(
    const ulonglong2 (&w1p)[16], const ulonglong2 (&w2p)[8],
    const ulonglong2 (&w3ap)[8], const ulonglong2 (&w3bp)[8],
    float b1l, float b2l, float b3a, float b3b,
    float* __restrict__ sbuf, float* __restrict__ sh1, float* __restrict__ sh2,
    int lane,
    float a0, float a1, float& o0, float& o1)
{
    // ---- stage argument into smem (lane owns dims lane, lane+32) ----
    sbuf[lane]      = a0;
    sbuf[lane + 32] = a1;
    __syncwarp();

    // ---- layer 1: 64-dim input ----
    unsigned long long acc01 = 0ull, acc23 = 0ull;
    const ulonglong2* v64 = reinterpret_cast<const ulonglong2*>(sbuf);
    #pragma unroll
    for (int i = 0; i < 16; ++i) {
        ulonglong2 v = v64[i];        // (dims 4i,4i+1), (dims 4i+2,4i+3)
        acc01 = ffma2(w1p[i].x, v.x, acc01);
        acc23 = ffma2(w1p[i].y, v.y, acc23);
    }
    float2 a01 = unpack2(acc01);
    float2 a23 = unpack2(acc23);
    float h1 = softplus_f((a01.x + a01.y) + (a23.x + a23.y) + b1l);

    // ---- layer 2: 32-dim ----
    sh1[lane] = h1;
    __syncwarp();
    unsigned long long s01 = 0ull, s23 = 0ull;
    const ulonglong2* v32 = reinterpret_cast<const ulonglong2*>(sh1);
    #pragma unroll
    for (int i = 0; i < 8; ++i) {
        ulonglong2 v = v32[i];
        s01 = ffma2(w2p[i].x, v.x, s01);
        s23 = ffma2(w2p[i].y, v.y, s23);
    }
    float2 sA = unpack2(s01);
    float2 sB = unpack2(s23);
    float h2 = softplus_f((sA.x + sA.y) + (sB.x + sB.y) + b2l);

    // ---- layer 3: two 32-dim outputs per lane ----
    sh2[lane] = h2;
    __syncwarp();
    unsigned long long p01 = 0ull, p23 = 0ull, q01 = 0ull, q23 = 0ull;
    const ulonglong2* h24 = reinterpret_cast<const ulonglong2*>(sh2);
    #pragma unroll
    for (int i = 0; i < 8; ++i) {
        ulonglong2 v = h24[i];
        p01 = ffma2(w3ap[i].x, v.x, p01);
        p23 = ffma2(w3ap[i].y, v.y, p23);
        q01 = ffma2(w3bp[i].x, v.x, q01);
        q23 = ffma2(w3bp[i].y, v.y, q23);
    }
    float2 pA = unpack2(p01);
    float2 pB = unpack2(p23);
    float2 qA = unpack2(q01);
    float2 qB = unpack2(q23);
    o0 = (pA.x + pA.y) + (pB.x + pB.y) + b3a;
    o1 = (qA.x + qA.y) + (qB.x + qB.y) + b3b;
}

__global__ void __launch_bounds__(64)
ode_kernel(const float* __restrict__ x0s,
           const float* __restrict__ W1, const float* __restrict__ b1,
           const float* __restrict__ W2, const float* __restrict__ b2,
           const float* __restrict__ W3, const float* __restrict__ b3,
           const int*   __restrict__ Tp,
           float* __restrict__ out, float* __restrict__ nsum_out, int B)
{
    __shared__ __align__(16) float s_arg[2][64];
    __shared__ __align__(16) float s_h1[2][32];
    __shared__ __align__(16) float s_h2[2][32];

    const int warp  = (blockIdx.x * blockDim.x + threadIdx.x) >> 5;
    const int wloc  = (threadIdx.x >> 5) & 1;
    const int lane  = threadIdx.x & 31;
    if (warp >= B) return;

    float* sbuf = s_arg[wloc];
    float* sh1  = s_h1[wloc];
    float* sh2  = s_h2[wloc];

    int   Ti = *Tp;
    float Tf;
    if (Ti > 0 && Ti < 1000000) Tf = (float)Ti;
    else                        Tf = __int_as_float(Ti);
    const float delta = Tf / 10.0f;

    // ---------------- weights to packed registers ----------------
    // Row-major rows are contiguous => float pairs load directly as u64 pairs.
    ulonglong2 w1p[16], w2p[8], w3ap[8], w3bp[8];
    {
        const ulonglong2* p = reinterpret_cast<const ulonglong2*>(W1 + lane * 64);
        #pragma unroll
        for (int i = 0; i < 16; ++i) w1p[i] = p[i];
    }
    {
        const ulonglong2* p = reinterpret_cast<const ulonglong2*>(W2 + lane * 32);
        #pragma unroll
        for (int i = 0; i < 8; ++i) w2p[i] = p[i];
    }
    {
        const ulonglong2* pa = reinterpret_cast<const ulonglong2*>(W3 + lane * 32);
        const ulonglong2* pb = reinterpret_cast<const ulonglong2*>(W3 + (lane + 32) * 32);
        #pragma unroll
        for (int i = 0; i < 8; ++i) { w3ap[i] = pa[i]; w3bp[i] = pb[i]; }
    }
    const float b1l = b1[lane], b2l = b2[lane];
    const float b3a = b3[lane], b3bv = b3[lane + 32];

    // ---------------- state ----------------
    float y0 = x0s[(size_t)warp * 64 + lane];
    float y1 = x0s[(size_t)warp * 64 + 32 + lane];
    float t  = 0.0f;
    float dt = 1e-3f;
    int   n  = 0;

    const size_t obase = (size_t)warp * 11 * 64;
    out[obase + lane]      = y0;
    out[obase + 32 + lane] = y1;

    const float A21f = 0.161f;
    const float A31f = -0.008480655492356989f, A32f = 0.335480655492357f;
    const float A41f = 2.8971530571054935f, A42f = -6.359448489975075f, A43f = 4.3622954328695815f;
    const float A51f = 5.325864828439257f, A52f = -11.748883564062828f, A53f = 7.4955393428898365f, A54f = -0.09249506636175525f;
    const float A61f = 5.86145544294642f, A62f = -12.92096931784711f, A63f = 8.159367898576159f, A64f = -0.071584973281401f, A65f = -0.028269050394068383f;
    const float B1f = 0.09646076681806523f, B2f = 0.01f, B3f = 0.4798896504144996f,
                B4f = 1.379008574103742f, B5f = -3.290069515436081f, B6f = 2.324710524099774f;
    const float E1f = -0.00178001105222577714f, E2f = -0.0008164344596567469f, E3f = 0.007880878010261995f,
                E4f = -0.1447110071732629f, E5f = 0.5823571654525552f, E6f = -0.45808210592918697f,
                E7f = 0.015151515151515152f;

    // FSAL invariant: k1 == f(y) at loop top. accept => k1 := k7 (bit-identical
    // to recomputing f(y5)); reject => unchanged. Matches reference numerics.
    float k1_0, k1_1;
    mlp_eval(w1p, w2p, w3ap, w3bp, b1l, b2l, b3a, b3bv, sbuf, sh1, sh2, lane,
             y0, y1, k1_0, k1_1);

    for (int iv = 1; iv <= 10; ++iv) {
        const float t_target = (float)iv * delta;
        for (int it = 0; it < 64; ++it) {
            float remaining = t_target - t;
            if (remaining <= 1e-12f) break;
            float h = fminf(dt, fmaxf(remaining, 0.0f));

            float k2_0, k2_1, k3_0, k3_1, k4_0, k4_1;
            float k5_0, k5_1, k6_0, k6_1, k7_0, k7_1;
            float a0, a1, s0, s1;

            a0 = fmaf(h, A21f * k1_0, y0);
            a1 = fmaf(h, A21f * k1_1, y1);
            mlp_eval(w1p, w2p, w3ap, w3bp, b1l, b2l, b3a, b3bv, sbuf, sh1, sh2, lane,
                     a0, a1, k2_0, k2_1);

            s0 = fmaf(A31f, k1_0, A32f * k2_0);
            s1 = fmaf(A31f, k1_1, A32f * k2_1);
            a0 = fmaf(h, s0, y0); a1 = fmaf(h, s1, y1);
            mlp_eval(w1p, w2p, w3ap, w3bp, b1l, b2l, b3a, b3bv, sbuf, sh1, sh2, lane,
                     a0, a1, k3_0, k3_1);

            s0 = fmaf(A41f, k1_0, fmaf(A42f, k2_0, A43f * k3_0));
            s1 = fmaf(A41f, k1_1, fmaf(A42f, k2_1, A43f * k3_1));
            a0 = fmaf(h, s0, y0); a1 = fmaf(h, s1, y1);
            mlp_eval(w1p, w2p, w3ap, w3bp, b1l, b2l, b3a, b3bv, sbuf, sh1, sh2, lane,
                     a0, a1, k4_0, k4_1);

            s0 = fmaf(A51f, k1_0, fmaf(A52f, k2_0, fmaf(A53f, k3_0, A54f * k4_0)));
            s1 = fmaf(A51f, k1_1, fmaf(A52f, k2_1, fmaf(A53f, k3_1, A54f * k4_1)));
            a0 = fmaf(h, s0, y0); a1 = fmaf(h, s1, y1);
            mlp_eval(w1p, w2p, w3ap, w3bp, b1l, b2l, b3a, b3bv, sbuf, sh1, sh2, lane,
                     a0, a1, k5_0, k5_1);

            s0 = fmaf(A61f, k1_0, fmaf(A62f, k2_0, fmaf(A63f, k3_0, fmaf(A64f, k4_0, A65f * k5_0))));
            s1 = fmaf(A61f, k1_1, fmaf(A62f, k2_1, fmaf(A63f, k3_1, fmaf(A64f, k4_1, A65f * k5_1))));
            a0 = fmaf(h, s0, y0); a1 = fmaf(h, s1, y1);
            mlp_eval(w1p, w2p, w3ap, w3bp, b1l, b2l, b3a, b3bv, sbuf, sh1, sh2, lane,
                     a0, a1, k6_0, k6_1);

            s0 = fmaf(B1f, k1_0, fmaf(B2f, k2_0, fmaf(B3f, k3_0, fmaf(B4f, k4_0, fmaf(B5f, k5_0, B6f * k6_0)))));
            s1 = fmaf(B1f, k1_1, fmaf(B2f, k2_1, fmaf(B3f, k3_1, fmaf(B4f, k4_1, fmaf(B5f, k5_1, B6f * k6_1)))));
            float y5_0 = fmaf(h, s0, y0);
            float y5_1 = fmaf(h, s1, y1);
            mlp_eval(w1p, w2p, w3ap, w3bp, b1l, b2l, b3a, b3bv, sbuf, sh1, sh2, lane,
                     y5_0, y5_1, k7_0, k7_1);

            float e0 = fmaf(E1f, k1_0, fmaf(E2f, k2_0, fmaf(E3f, k3_0, fmaf(E4f, k4_0,
                       fmaf(E5f, k5_0, fmaf(E6f, k6_0, E7f * k7_0))))));
            float e1 = fmaf(E1f, k1_1, fmaf(E2f, k2_1, fmaf(E3f, k3_1, fmaf(E4f, k4_1,
                       fmaf(E5f, k5_1, fmaf(E6f, k6_1, E7f * k7_1))))));
            float err0 = h * e0, err1 = h * e1;
            float sc0 = fmaf(1e-3f, fmaxf(fabsf(y0), fabsf(y5_0)), 1e-6f);
            float sc1 = fmaf(1e-3f, fmaxf(fabsf(y1), fabsf(y5_1)), 1e-6f);
            float r0 = err0 / sc0, r1 = err1 / sc1;
            float local = fmaf(r0, r0, r1 * r1);
            #pragma unroll
            for (int off = 16; off > 0; off >>= 1)
                local += __shfl_xor_sync(WMASK, local, off);
            float enorm = fmaxf(sqrtf(local * (1.0f / 64.0f)), 1e-10f);

            bool accept = (enorm <= 1.0f);
            float fac = fminf(fmaxf(0.9f * powf(enorm, -0.2f), 0.1f), 5.0f);
            if (accept) {
                t += h; y0 = y5_0; y1 = y5_1;
                k1_0 = k7_0; k1_1 = k7_1;   // FSAL
            }
            dt = fmaxf(h * fac, 1e-8f);
            n += 1;
        }
        out[obase + (size_t)iv * 64 + lane]      = y0;
        out[obase + (size_t)iv * 64 + 32 + lane] = y1;
    }

    if (lane == 0) atomicAdd(nsum_out, (float)n);
}

// Only used if the output tail has more than one element (expected: exactly 1).
__global__ void replicate_tail_kernel(float* tail, long long tail_elems) {
    long long i = (long long)blockIdx.x * blockDim.x + threadIdx.x;
    if (i > 0 && i < tail_elems) tail[i] = tail[0];
}

extern "C" void kernel_launch(void* const* d_in, const int* in_sizes, int n_in,
                              void* d_out, int out_size) {
    const float* x0s = (const float*)d_in[0];
    const float* W1  = (const float*)d_in[1];
    const float* b1  = (const float*)d_in[2];
    const float* W2  = (const float*)d_in[3];
    const float* b2  = (const float*)d_in[4];
    const float* W3  = (const float*)d_in[5];
    const float* b3  = (const float*)d_in[6];
    const int*   Tp  = (const int*)d_in[7];
    float* out = (float*)d_out;

    const int B = in_sizes[0] / 64;
    const long long traj_elems = (long long)B * 11 * 64;
    const long long tail = (long long)out_size - traj_elems;

    if (tail > 0)
        cudaMemsetAsync(out + traj_elems, 0, (size_t)tail * sizeof(float), 0);

    const int threads = 64;
    const int blocks = (B * 32 + threads - 1) / threads;
    ode_kernel<<<blocks, threads>>>(x0s, W1, b1, W2, b2, W3, b3, Tp,
                                    out, out + traj_elems, B);

    if (tail > 1) {
        int tb = (int)((tail + 63) / 64);
        replicate_tail_kernel<<<tb, 64>>>(out + traj_elems, tail);
    }
}

// round 13
// speedup vs baseline: 1.4882x; 1.0286x over previous
#include <cuda_runtime.h>
#include <math.h>

#define WMASK 0xffffffffu

// ---- packed f32x2 helpers (sm_100+) ----
// NOTE: only fma.rn.f32x2 is used. add.rn.f32x2 is deliberately avoided —
// both container-level failures in this session correlate exactly with its
// introduction; partial merges are done with scalar adds instead.
__device__ __forceinline__ unsigned long long ffma2(
    unsigned long long a, unsigned long long b, unsigned long long c)
{
    unsigned long long d;
    asm("fma.rn.f32x2 %0, %1, %2, %3;" : "=l"(d) : "l"(a), "l"(b), "l"(c));
    return d;
}
__device__ __forceinline__ float2 unpack2(unsigned long long v) {
    float2 r;
    asm("mov.b64 {%0, %1}, %2;" : "=f"(r.x), "=f"(r.y) : "l"(v));
    return r;
}
__device__ __forceinline__ unsigned long long pack2(float lo, float hi) {
    unsigned long long v;
    asm("mov.b64 %0, {%1, %2};" : "=l"(v) : "f"(lo), "f"(hi));
    return v;
}

__device__ __forceinline__ float softplus_f(float x) {
    // jax.nn.softplus = max(x,0) + log1p(exp(-|x|))
    return fmaxf(x, 0.0f) + log1pf(expf(-fabsf(x)));
}

// Warp-uniform broadcast matvec via shared memory + packed f32x2 FMAs,
// with split (4-way / 8-way) accumulator chains to halve dependency depth.
// Biases are folded into accumulator init. Partial accumulators are merged
// with scalar adds (balanced tree) after unpacking.
__device__ __forceinline__ void mlp_eval(
    const ulonglong2 (&w1p)[16], const ulonglong2 (&w2p)[8],
    const ulonglong2 (&w3ap)[8], const ulonglong2 (&w3bp)[8],
    float b1l, float b2l, float b3a, float b3b,
    float* __restrict__ sbuf, float* __restrict__ sh1, float* __restrict__ sh2,
    int lane,
    float a0, float a1, float& o0, float& o1)
{
    // ---- stage argument into smem (lane owns dims lane, lane+32) ----
    sbuf[lane]      = a0;
    sbuf[lane + 32] = a1;
    __syncwarp();

    // ---- layer 1: 64-dim input, 4 packed chains of depth 8 ----
    unsigned long long acc01a = pack2(b1l, 0.0f), acc23a = 0ull;
    unsigned long long acc01b = 0ull,             acc23b = 0ull;
    const ulonglong2* v64 = reinterpret_cast<const ulonglong2*>(sbuf);
    #pragma unroll
    for (int i = 0; i < 8; ++i) {
        ulonglong2 va = v64[i];
        acc01a = ffma2(w1p[i].x, va.x, acc01a);
        acc23a = ffma2(w1p[i].y, va.y, acc23a);
        ulonglong2 vb = v64[i + 8];
        acc01b = ffma2(w1p[i + 8].x, vb.x, acc01b);
        acc23b = ffma2(w1p[i + 8].y, vb.y, acc23b);
    }
    {
        float2 ua = unpack2(acc01a);
        float2 ub = unpack2(acc01b);
        float2 va = unpack2(acc23a);
        float2 vb = unpack2(acc23b);
        float h1 = softplus_f(((ua.x + ub.x) + (ua.y + ub.y)) +
                              ((va.x + vb.x) + (va.y + vb.y)));
        sh1[lane] = h1;
    }
    __syncwarp();

    // ---- layer 2: 32-dim, 4 packed chains of depth 4 ----
    unsigned long long s01a = pack2(b2l, 0.0f), s23a = 0ull;
    unsigned long long s01b = 0ull,             s23b = 0ull;
    const ulonglong2* v32 = reinterpret_cast<const ulonglong2*>(sh1);
    #pragma unroll
    for (int i = 0; i < 4; ++i) {
        ulonglong2 va = v32[i];
        s01a = ffma2(w2p[i].x, va.x, s01a);
        s23a = ffma2(w2p[i].y, va.y, s23a);
        ulonglong2 vb = v32[i + 4];
        s01b = ffma2(w2p[i + 4].x, vb.x, s01b);
        s23b = ffma2(w2p[i + 4].y, vb.y, s23b);
    }
    {
        float2 ua = unpack2(s01a);
        float2 ub = unpack2(s01b);
        float2 va = unpack2(s23a);
        float2 vb = unpack2(s23b);
        float h2 = softplus_f(((ua.x + ub.x) + (ua.y + ub.y)) +
                              ((va.x + vb.x) + (va.y + vb.y)));
        sh2[lane] = h2;
    }
    __syncwarp();

    // ---- layer 3: two 32-dim outputs, 8 packed chains of depth 4 ----
    unsigned long long p01a = pack2(b3a, 0.0f), p23a = 0ull;
    unsigned long long p01b = 0ull,             p23b = 0ull;
    unsigned long long q01a = pack2(b3b, 0.0f), q23a = 0ull;
    unsigned long long q01b = 0ull,             q23b = 0ull;
    const ulonglong2* h24 = reinterpret_cast<const ulonglong2*>(sh2);
    #pragma unroll
    for (int i = 0; i < 4; ++i) {
        ulonglong2 va = h24[i];
        p01a = ffma2(w3ap[i].x, va.x, p01a);
        p23a = ffma2(w3ap[i].y, va.y, p23a);
        q01a = ffma2(w3bp[i].x, va.x, q01a);
        q23a = ffma2(w3bp[i].y, va.y, q23a);
        ulonglong2 vb = h24[i + 4];
        p01b = ffma2(w3ap[i + 4].x, vb.x, p01b);
        p23b = ffma2(w3ap[i + 4].y, vb.y, p23b);
        q01b = ffma2(w3bp[i + 4].x, vb.x, q01b);
        q23b = ffma2(w3bp[i + 4].y, vb.y, q23b);
    }
    {
        float2 pa = unpack2(p01a);
        float2 pb = unpack2(p01b);
        float2 pc = unpack2(p23a);
        float2 pd = unpack2(p23b);
        o0 = ((pa.x + pb.x) + (pa.y + pb.y)) + ((pc.x + pd.x) + (pc.y + pd.y));
        float2 qa = unpack2(q01a);
        float2 qb = unpack2(q01b);
        float2 qc = unpack2(q23a);
        float2 qd = unpack2(q23b);
        o1 = ((qa.x + qb.x) + (qa.y + qb.y)) + ((qc.x + qd.x) + (qc.y + qd.y));
    }
}

__global__ void __launch_bounds__(64)
ode_kernel(const float* __restrict__ x0s,
           const float* __restrict__ W1, const float* __restrict__ b1,
           const float* __restrict__ W2, const float* __restrict__ b2,
           const float* __restrict__ W3, const float* __restrict__ b3,
           const int*   __restrict__ Tp,
           float* __restrict__ out, float* __restrict__ nsum_out, int B)
{
    __shared__ __align__(16) float s_arg[2][64];
    __shared__ __align__(16) float s_h1[2][32];
    __shared__ __align__(16) float s_h2[2][32];

    const int warp  = (blockIdx.x * blockDim.x + threadIdx.x) >> 5;
    const int wloc  = (threadIdx.x >> 5) & 1;
    const int lane  = threadIdx.x & 31;
    if (warp >= B) return;

    float* sbuf = s_arg[wloc];
    float* sh1  = s_h1[wloc];
    float* sh2  = s_h2[wloc];

    int   Ti = *Tp;
    float Tf;
    if (Ti > 0 && Ti < 1000000) Tf = (float)Ti;
    else                        Tf = __int_as_float(Ti);
    const float delta = Tf / 10.0f;

    // ---------------- weights to packed registers ----------------
    ulonglong2 w1p[16], w2p[8], w3ap[8], w3bp[8];
    {
        const ulonglong2* p = reinterpret_cast<const ulonglong2*>(W1 + lane * 64);
        #pragma unroll
        for (int i = 0; i < 16; ++i) w1p[i] = p[i];
    }
    {
        const ulonglong2* p = reinterpret_cast<const ulonglong2*>(W2 + lane * 32);
        #pragma unroll
        for (int i = 0; i < 8; ++i) w2p[i] = p[i];
    }
    {
        const ulonglong2* pa = reinterpret_cast<const ulonglong2*>(W3 + lane * 32);
        const ulonglong2* pb = reinterpret_cast<const ulonglong2*>(W3 + (lane + 32) * 32);
        #pragma unroll
        for (int i = 0; i < 8; ++i) { w3ap[i] = pa[i]; w3bp[i] = pb[i]; }
    }
    const float b1l = b1[lane], b2l = b2[lane];
    const float b3a = b3[lane], b3bv = b3[lane + 32];

    // ---------------- state ----------------
    float y0 = x0s[(size_t)warp * 64 + lane];
    float y1 = x0s[(size_t)warp * 64 + 32 + lane];
    float t  = 0.0f;
    float dt = 1e-3f;
    int   n  = 0;

    const size_t obase = (size_t)warp * 11 * 64;
    out[obase + lane]      = y0;
    out[obase + 32 + lane] = y1;

    const float A21f = 0.161f;
    const float A31f = -0.008480655492356989f, A32f = 0.335480655492357f;
    const float A41f = 2.8971530571054935f, A42f = -6.359448489975075f, A43f = 4.3622954328695815f;
    const float A51f = 5.325864828439257f, A52f = -11.748883564062828f, A53f = 7.4955393428898365f, A54f = -0.09249506636175525f;
    const float A61f = 5.86145544294642f, A62f = -12.92096931784711f, A63f = 8.159367898576159f, A64f = -0.071584973281401f, A65f = -0.028269050394068383f;
    const float B1f = 0.09646076681806523f, B2f = 0.01f, B3f = 0.4798896504144996f,
                B4f = 1.379008574103742f, B5f = -3.290069515436081f, B6f = 2.324710524099774f;
    const float E1f = -0.00178001105222577714f, E2f = -0.0008164344596567469f, E3f = 0.007880878010261995f,
                E4f = -0.1447110071732629f, E5f = 0.5823571654525552f, E6f = -0.45808210592918697f,
                E7f = 0.015151515151515152f;

    // FSAL invariant: k1 == f(y) at loop top.
    float k1_0, k1_1;
    mlp_eval(w1p, w2p, w3ap, w3bp, b1l, b2l, b3a, b3bv, sbuf, sh1, sh2, lane,
             y0, y1, k1_0, k1_1);

    for (int iv = 1; iv <= 10; ++iv) {
        const float t_target = (float)iv * delta;
        for (int it = 0; it < 64; ++it) {
            float remaining = t_target - t;
            if (remaining <= 1e-12f) break;
            float h = fminf(dt, fmaxf(remaining, 0.0f));

            float k2_0, k2_1, k3_0, k3_1, k4_0, k4_1;
            float k5_0, k5_1, k6_0, k6_1, k7_0, k7_1;
            float a0, a1, s0, s1;

            a0 = fmaf(h, A21f * k1_0, y0);
            a1 = fmaf(h, A21f * k1_1, y1);
            mlp_eval(w1p, w2p, w3ap, w3bp, b1l, b2l, b3a, b3bv, sbuf, sh1, sh2, lane,
                     a0, a1, k2_0, k2_1);

            s0 = fmaf(A31f, k1_0, A32f * k2_0);
            s1 = fmaf(A31f, k1_1, A32f * k2_1);
            a0 = fmaf(h, s0, y0); a1 = fmaf(h, s1, y1);
            mlp_eval(w1p, w2p, w3ap, w3bp, b1l, b2l, b3a, b3bv, sbuf, sh1, sh2, lane,
                     a0, a1, k3_0, k3_1);

            s0 = fmaf(A41f, k1_0, fmaf(A42f, k2_0, A43f * k3_0));
            s1 = fmaf(A41f, k1_1, fmaf(A42f, k2_1, A43f * k3_1));
            a0 = fmaf(h, s0, y0); a1 = fmaf(h, s1, y1);
            mlp_eval(w1p, w2p, w3ap, w3bp, b1l, b2l, b3a, b3bv, sbuf, sh1, sh2, lane,
                     a0, a1, k4_0, k4_1);

            s0 = fmaf(A51f, k1_0, fmaf(A52f, k2_0, fmaf(A53f, k3_0, A54f * k4_0)));
            s1 = fmaf(A51f, k1_1, fmaf(A52f, k2_1, fmaf(A53f, k3_1, A54f * k4_1)));
            a0 = fmaf(h, s0, y0); a1 = fmaf(h, s1, y1);
            mlp_eval(w1p, w2p, w3ap, w3bp, b1l, b2l, b3a, b3bv, sbuf, sh1, sh2, lane,
                     a0, a1, k5_0, k5_1);

            s0 = fmaf(A61f, k1_0, fmaf(A62f, k2_0, fmaf(A63f, k3_0, fmaf(A64f, k4_0, A65f * k5_0))));
            s1 = fmaf(A61f, k1_1, fmaf(A62f, k2_1, fmaf(A63f, k3_1, fmaf(A64f, k4_1, A65f * k5_1))));
            a0 = fmaf(h, s0, y0); a1 = fmaf(h, s1, y1);
            mlp_eval(w1p, w2p, w3ap, w3bp, b1l, b2l, b3a, b3bv, sbuf, sh1, sh2, lane,
                     a0, a1, k6_0, k6_1);

            s0 = fmaf(B1f, k1_0, fmaf(B2f, k2_0, fmaf(B3f, k3_0, fmaf(B4f, k4_0, fmaf(B5f, k5_0, B6f * k6_0)))));
            s1 = fmaf(B1f, k1_1, fmaf(B2f, k2_1, fmaf(B3f, k3_1, fmaf(B4f, k4_1, fmaf(B5f, k5_1, B6f * k6_1)))));
            float y5_0 = fmaf(h, s0, y0);
            float y5_1 = fmaf(h, s1, y1);
            mlp_eval(w1p, w2p, w3ap, w3bp, b1l, b2l, b3a, b3bv, sbuf, sh1, sh2, lane,
                     y5_0, y5_1, k7_0, k7_1);

            float e0 = fmaf(E1f, k1_0, fmaf(E2f, k2_0, fmaf(E3f, k3_0, fmaf(E4f, k4_0,
                       fmaf(E5f, k5_0, fmaf(E6f, k6_0, E7f * k7_0))))));
            float e1 = fmaf(E1f, k1_1, fmaf(E2f, k2_1, fmaf(E3f, k3_1, fmaf(E4f, k4_1,
                       fmaf(E5f, k5_1, fmaf(E6f, k6_1, E7f * k7_1))))));
            float err0 = h * e0, err1 = h * e1;
            float sc0 = fmaf(1e-3f, fmaxf(fabsf(y0), fabsf(y5_0)), 1e-6f);
            float sc1 = fmaf(1e-3f, fmaxf(fabsf(y1), fabsf(y5_1)), 1e-6f);
            float r0 = err0 / sc0, r1 = err1 / sc1;
            float local = fmaf(r0, r0, r1 * r1);
            #pragma unroll
            for (int off = 16; off > 0; off >>= 1)
                local += __shfl_xor_sync(WMASK, local, off);
            float enorm = fmaxf(sqrtf(local * (1.0f / 64.0f)), 1e-10f);

            bool accept = (enorm <= 1.0f);
            // fac only scales dt (step-size controller); accept uses enorm.
            float fac = fminf(fmaxf(0.9f * __powf(enorm, -0.2f), 0.1f), 5.0f);
            if (accept) {
                t += h; y0 = y5_0; y1 = y5_1;
                k1_0 = k7_0; k1_1 = k7_1;   // FSAL
            }
            dt = fmaxf(h * fac, 1e-8f);
            n += 1;
        }
        out[obase + (size_t)iv * 64 + lane]      = y0;
        out[obase + (size_t)iv * 64 + 32 + lane] = y1;
    }

    if (lane == 0) atomicAdd(nsum_out, (float)n);
}

// Only used if the output tail has more than one element (expected: exactly 1).
__global__ void replicate_tail_kernel(float* tail, long long tail_elems) {
    long long i = (long long)blockIdx.x * blockDim.x + threadIdx.x;
    if (i > 0 && i < tail_elems) tail[i] = tail[0];
}

extern "C" void kernel_launch(void* const* d_in, const int* in_sizes, int n_in,
                              void* d_out, int out_size) {
    const float* x0s = (const float*)d_in[0];
    const float* W1  = (const float*)d_in[1];
    const float* b1  = (const float*)d_in[2];
    const float* W2  = (const float*)d_in[3];
    const float* b2  = (const float*)d_in[4];
    const float* W3  = (const float*)d_in[5];
    const float* b3  = (const float*)d_in[6];
    const int*   Tp  = (const int*)d_in[7];
    float* out = (float*)d_out;

    const int B = in_sizes[0] / 64;
    const long long traj_elems = (long long)B * 11 * 64;
    const long long tail = (long long)out_size - traj_elems;

    if (tail > 0)
        cudaMemsetAsync(out + traj_elems, 0, (size_t)tail * sizeof(float), 0);

    const int threads = 64;
    const int blocks = (B * 32 + threads - 1) / threads;
    ode_kernel<<<blocks, threads>>>(x0s, W1, b1, W2, b2, W3, b3, Tp,
                                    out, out + traj_elems, B);

    if (tail > 1) {
        int tb = (int)((tail + 63) / 64);
        replicate_tail_kernel<<<tb, 64>>>(out + traj_elems, tail);
    }
}